// round 1
// baseline (speedup 1.0000x reference)
#include <cuda_runtime.h>
#include <math.h>

#define EDIM 1024
#define NH   16
#define HD   64
#define BB   2
#define SS   2048
#define MTOT (BB*SS)   // 4096

// Scratch (static device globals — no allocation in kernel_launch)
__device__ float g_Q[MTOT*EDIM];
__device__ float g_K[MTOT*EDIM];
__device__ float g_V[MTOT*EDIM];
__device__ float g_ctx[MTOT*EDIM];

// ---------------------------------------------------------------------------
// GEMM: C[M,N] = A[M,K] @ W[K,N] + bias.  M=4096, N=K=1024.
// 64x64 tile, BK=16, 256 threads, 4x4 micro-tile per thread.
// head_layout=1: write to [B,H,S,D] (for Q/K/V). head_layout=0: row-major.
// ---------------------------------------------------------------------------
__global__ __launch_bounds__(256)
void gemm_bias(const float* __restrict__ A, const float* __restrict__ W,
               const float* __restrict__ bias, float* __restrict__ C,
               int head_layout)
{
    __shared__ float As[16][68];   // [k][m], pad to 68 to soften bank conflicts
    __shared__ float Bs[16][68];   // [k][n]

    const int tid = threadIdx.x;
    const int tx = tid & 15;       // n direction
    const int ty = tid >> 4;       // m direction
    const int m0 = blockIdx.x * 64;
    const int n0 = blockIdx.y * 64;

    float acc[4][4];
#pragma unroll
    for (int i = 0; i < 4; i++)
#pragma unroll
        for (int j = 0; j < 4; j++) acc[i][j] = 0.f;

    for (int k0 = 0; k0 < EDIM; k0 += 16) {
        // Load A tile: 64 rows x 16 k. thread -> row tid>>2, kcol (tid&3)*4
        {
            int r  = tid >> 2;
            int kc = (tid & 3) * 4;
            float4 a = *reinterpret_cast<const float4*>(&A[(size_t)(m0 + r) * EDIM + k0 + kc]);
            As[kc + 0][r] = a.x;
            As[kc + 1][r] = a.y;
            As[kc + 2][r] = a.z;
            As[kc + 3][r] = a.w;
        }
        // Load W tile: 16 k x 64 n. thread -> k row tid>>4, ncol (tid&15)*4
        {
            int kr = tid >> 4;
            int nc = (tid & 15) * 4;
            float4 b = *reinterpret_cast<const float4*>(&W[(size_t)(k0 + kr) * EDIM + n0 + nc]);
            *reinterpret_cast<float4*>(&Bs[kr][nc]) = b;
        }
        __syncthreads();

#pragma unroll
        for (int k = 0; k < 16; k++) {
            float4 a = *reinterpret_cast<const float4*>(&As[k][ty * 4]);
            float4 b = *reinterpret_cast<const float4*>(&Bs[k][tx * 4]);
            acc[0][0] += a.x * b.x; acc[0][1] += a.x * b.y; acc[0][2] += a.x * b.z; acc[0][3] += a.x * b.w;
            acc[1][0] += a.y * b.x; acc[1][1] += a.y * b.y; acc[1][2] += a.y * b.z; acc[1][3] += a.y * b.w;
            acc[2][0] += a.z * b.x; acc[2][1] += a.z * b.y; acc[2][2] += a.z * b.z; acc[2][3] += a.z * b.w;
            acc[3][0] += a.w * b.x; acc[3][1] += a.w * b.y; acc[3][2] += a.w * b.z; acc[3][3] += a.w * b.w;
        }
        __syncthreads();
    }

    const int n = n0 + tx * 4;
    float4 bv = *reinterpret_cast<const float4*>(&bias[n]);

#pragma unroll
    for (int i = 0; i < 4; i++) {
        int m = m0 + ty * 4 + i;
        float4 r;
        r.x = acc[i][0] + bv.x;
        r.y = acc[i][1] + bv.y;
        r.z = acc[i][2] + bv.z;
        r.w = acc[i][3] + bv.w;
        if (head_layout) {
            int b_ = m >> 11;          // /S
            int s_ = m & (SS - 1);
            int h  = n >> 6;           // /HD  (all 4 cols in same head: n%4==0, HD=64)
            int d  = n & (HD - 1);
            float* dst = C + (((size_t)(b_ * NH + h) * SS + s_) * HD + d);
            *reinterpret_cast<float4*>(dst) = r;
        } else {
            *reinterpret_cast<float4*>(&C[(size_t)m * EDIM + n]) = r;
        }
    }
}

// ---------------------------------------------------------------------------
// Flash-style attention: 1 query row per thread, online softmax.
// grid = (S/128, B*H), block = 128.
// K/V read from [B,H,S,D]; ctx written to [B,S,E] (head-interleaved).
// ---------------------------------------------------------------------------
__global__ __launch_bounds__(128)
void attn_kernel(const float* __restrict__ mask)
{
    const int bh = blockIdx.y;        // 0..31
    const int b_ = bh >> 4;
    const int h  = bh & (NH - 1);
    const int qi = blockIdx.x * 128 + threadIdx.x;   // query index in S

    __shared__ float Ks[32 * HD];
    __shared__ float Vs[32 * HD];
    __shared__ float madd[32];

    // load q row into registers
    float q[HD];
    {
        const float* Qp = g_Q + ((size_t)bh * SS + qi) * HD;
#pragma unroll
        for (int i = 0; i < 16; i++) {
            float4 t = *reinterpret_cast<const float4*>(&Qp[i * 4]);
            q[i * 4 + 0] = t.x; q[i * 4 + 1] = t.y; q[i * 4 + 2] = t.z; q[i * 4 + 3] = t.w;
        }
    }

    float acc[HD];
#pragma unroll
    for (int d = 0; d < HD; d++) acc[d] = 0.f;
    float mval = -1e30f;
    float l = 0.f;

    const float scale = 0.125f;  // 1/sqrt(64)

    for (int k0 = 0; k0 < SS; k0 += 32) {
        // cooperative tile load: 32 keys x 64 floats = 512 float4 / 128 threads
        const float4* Kp = reinterpret_cast<const float4*>(g_K + ((size_t)bh * SS + k0) * HD);
        const float4* Vp = reinterpret_cast<const float4*>(g_V + ((size_t)bh * SS + k0) * HD);
        float4* Ks4 = reinterpret_cast<float4*>(Ks);
        float4* Vs4 = reinterpret_cast<float4*>(Vs);
#pragma unroll
        for (int i = 0; i < 4; i++) {
            Ks4[i * 128 + threadIdx.x] = Kp[i * 128 + threadIdx.x];
            Vs4[i * 128 + threadIdx.x] = Vp[i * 128 + threadIdx.x];
        }
        if (threadIdx.x < 32)
            madd[threadIdx.x] = (1.0f - mask[b_ * SS + k0 + threadIdx.x]) * -10000.0f;
        __syncthreads();

        const float4* Kt = reinterpret_cast<const float4*>(Ks);
        const float4* Vt = reinterpret_cast<const float4*>(Vs);

#pragma unroll 4
        for (int j = 0; j < 32; j++) {
            float s = 0.f;
#pragma unroll
            for (int d4 = 0; d4 < 16; d4++) {
                float4 kk = Kt[j * 16 + d4];
                s += q[d4 * 4 + 0] * kk.x;
                s += q[d4 * 4 + 1] * kk.y;
                s += q[d4 * 4 + 2] * kk.z;
                s += q[d4 * 4 + 3] * kk.w;
            }
            s = s * scale + madd[j];

            float mn = fmaxf(mval, s);
            float p;
            if (mn > mval) {
                float corr = __expf(mval - mn);   // 0 on first key
                l *= corr;
#pragma unroll
                for (int d = 0; d < HD; d++) acc[d] *= corr;
                mval = mn;
                p = 1.0f;                          // exp(s - s)
            } else {
                p = __expf(s - mval);
            }
            l += p;
#pragma unroll
            for (int d4 = 0; d4 < 16; d4++) {
                float4 vv = Vt[j * 16 + d4];
                acc[d4 * 4 + 0] += p * vv.x;
                acc[d4 * 4 + 1] += p * vv.y;
                acc[d4 * 4 + 2] += p * vv.z;
                acc[d4 * 4 + 3] += p * vv.w;
            }
        }
        __syncthreads();
    }

    float inv = 1.0f / l;
    float* Cp = g_ctx + ((size_t)(b_ * SS + qi) * EDIM) + h * HD;
#pragma unroll
    for (int d4 = 0; d4 < 16; d4++) {
        float4 r;
        r.x = acc[d4 * 4 + 0] * inv;
        r.y = acc[d4 * 4 + 1] * inv;
        r.z = acc[d4 * 4 + 2] * inv;
        r.w = acc[d4 * 4 + 3] * inv;
        *reinterpret_cast<float4*>(&Cp[d4 * 4]) = r;
    }
}

// ---------------------------------------------------------------------------
extern "C" void kernel_launch(void* const* d_in, const int* in_sizes, int n_in,
                              void* d_out, int out_size)
{
    const float* X    = (const float*)d_in[0];   // [B,S,E]
    const float* mask = (const float*)d_in[1];   // [B,S]
    const float* Wq   = (const float*)d_in[2];
    const float* bq   = (const float*)d_in[3];
    const float* Wk   = (const float*)d_in[4];
    const float* bk   = (const float*)d_in[5];
    const float* Wv   = (const float*)d_in[6];
    const float* bv   = (const float*)d_in[7];
    const float* Wo   = (const float*)d_in[8];
    const float* bo   = (const float*)d_in[9];
    float* out = (float*)d_out;

    float *Qd, *Kd, *Vd, *Cd;
    cudaGetSymbolAddress((void**)&Qd, g_Q);
    cudaGetSymbolAddress((void**)&Kd, g_K);
    cudaGetSymbolAddress((void**)&Vd, g_V);
    cudaGetSymbolAddress((void**)&Cd, g_ctx);

    dim3 ggrid(MTOT / 64, EDIM / 64);
    gemm_bias<<<ggrid, 256>>>(X, Wq, bq, Qd, 1);
    gemm_bias<<<ggrid, 256>>>(X, Wk, bk, Kd, 1);
    gemm_bias<<<ggrid, 256>>>(X, Wv, bv, Vd, 1);

    dim3 agrid(SS / 128, BB * NH);
    attn_kernel<<<agrid, 128>>>(mask);

    gemm_bias<<<ggrid, 256>>>(Cd, Wo, bo, out, 0);
}